// round 1
// baseline (speedup 1.0000x reference)
#include <cuda_runtime.h>

#define BATCH 50000
#define K 10
#define DIM 128
#define VECS_PER_ROW (DIM / 4)   // 32 float4 per row — one per lane

__global__ __launch_bounds__(256) void mean_agg_kernel(
    const int* __restrict__ nodes,        // [BATCH]
    const int* __restrict__ neighbours,   // [BATCH, K]
    const float4* __restrict__ features,  // [N_NODES, 32] as float4
    float4* __restrict__ out)             // [BATCH, 32] as float4
{
    const int warp = (blockIdx.x * blockDim.x + threadIdx.x) >> 5;
    const int lane = threadIdx.x & 31;
    if (warp >= BATCH) return;

    // Gather the 11 row ids (self + K neighbours). Same address across the
    // warp -> broadcast loads, cheap.
    int idx[K + 1];
    idx[0] = nodes[warp];
#pragma unroll
    for (int k = 0; k < K; k++) idx[k + 1] = neighbours[warp * K + k];

    // Front-batch all 11 gathered float4 loads (MLP=11) before summing so the
    // ~240-cycle L2 latency is overlapped.
    float4 v[K + 1];
#pragma unroll
    for (int k = 0; k < K + 1; k++) {
        v[k] = __ldg(&features[(long long)idx[k] * VECS_PER_ROW + lane]);
    }

    float4 acc = v[0];
#pragma unroll
    for (int k = 1; k < K + 1; k++) {
        acc.x += v[k].x;
        acc.y += v[k].y;
        acc.z += v[k].z;
        acc.w += v[k].w;
    }

    const float s = 1.0f / (float)(K + 1);
    acc.x *= s; acc.y *= s; acc.z *= s; acc.w *= s;

    out[(long long)warp * VECS_PER_ROW + lane] = acc;
}

extern "C" void kernel_launch(void* const* d_in, const int* in_sizes, int n_in,
                              void* d_out, int out_size)
{
    const int*    nodes      = (const int*)d_in[0];
    const int*    neighbours = (const int*)d_in[1];
    const float4* features   = (const float4*)d_in[2];
    float4*       out        = (float4*)d_out;

    // One warp per output row: 8 warps / 256-thread block.
    const int warps_per_block = 256 / 32;
    const int blocks = (BATCH + warps_per_block - 1) / warps_per_block;
    mean_agg_kernel<<<blocks, 256>>>(nodes, neighbours, features, out);
}